// round 6
// baseline (speedup 1.0000x reference)
#include <cuda_runtime.h>
#include <math.h>

#define B_   64
#define T_   256
#define E_   300
#define H_   512
#define D_   1024
#define G_   2048
#define OUT_ 256
#define NB_LSTM 128u

__device__ float g_embeds[B_*T_*E_];
__device__ float g_xpre_f[B_*T_*G_];
__device__ float g_xpre_b[B_*T_*G_];
__device__ float g_ctx[B_*T_*D_];
__device__ float g_target[B_*T_*D_];
__device__ float g_scores[B_*T_*T_];
__device__ float g_weighted[B_*T_*D_];
__device__ float g_htilde[B_*T_*D_];
__device__ float g_partial[2*16*B_*G_];
__device__ float g_ctxout[B_*D_];
__device__ float g_y[B_*OUT_];
__device__ unsigned g_bar;

__global__ void embed_kernel(const int* __restrict__ inp, const float* __restrict__ table) {
    int idx = blockIdx.x * blockDim.x + threadIdx.x;
    if (idx >= B_*T_*E_) return;
    int bt = idx / E_, e = idx - bt * E_;
    g_embeds[idx] = table[(long)inp[bt] * E_ + e];
}

// C = act(A*B(^T) + bias1 + bias2 [+C]).  A:[M,K] lda.  TRANSB: B:[N,K] ldb else [K,N] ldb.
template<bool TRANSB, bool ACCUM, bool TANH>
__global__ void __launch_bounds__(256) gemm_kernel(
    const float* __restrict__ A, const float* __restrict__ Bm,
    const float* __restrict__ bias1, const float* __restrict__ bias2,
    float* __restrict__ C, int M, int N, int K, int lda, int ldb, int ldc,
    long sA, long sB, long sC)
{
    __shared__ float As[8][128];
    __shared__ float Bs[8][128];
    int tid = threadIdx.x;
    int bm = blockIdx.y * 128, bn = blockIdx.x * 128, z = blockIdx.z;
    A += (long)z * sA; Bm += (long)z * sB; C += (long)z * sC;
    int tx = tid & 15, ty = tid >> 4;
    float acc[8][8];
#pragma unroll
    for (int i = 0; i < 8; i++)
#pragma unroll
        for (int j = 0; j < 8; j++) acc[i][j] = 0.f;
    int ar = tid >> 1, ak = (tid & 1) * 4;
    for (int kt = 0; kt < K; kt += 8) {
#pragma unroll
        for (int i = 0; i < 4; i++) {
            int k = kt + ak + i;
            As[ak + i][ar] = (k < K) ? A[(long)(bm + ar) * lda + k] : 0.f;
        }
        if (TRANSB) {
#pragma unroll
            for (int i = 0; i < 4; i++) {
                int k = kt + ak + i;
                Bs[ak + i][ar] = (k < K) ? Bm[(long)(bn + ar) * ldb + k] : 0.f;
            }
        } else {
            int bn_ = tid & 127, bk = (tid >> 7) * 4;
#pragma unroll
            for (int i = 0; i < 4; i++) {
                int k = kt + bk + i;
                Bs[bk + i][bn_] = (k < K) ? Bm[(long)k * ldb + bn + bn_] : 0.f;
            }
        }
        __syncthreads();
#pragma unroll
        for (int kk = 0; kk < 8; kk++) {
            float4 a0 = *(const float4*)&As[kk][ty * 8];
            float4 a1 = *(const float4*)&As[kk][ty * 8 + 4];
            float4 b0 = *(const float4*)&Bs[kk][tx * 8];
            float4 b1 = *(const float4*)&Bs[kk][tx * 8 + 4];
            float av[8] = {a0.x,a0.y,a0.z,a0.w,a1.x,a1.y,a1.z,a1.w};
            float bv[8] = {b0.x,b0.y,b0.z,b0.w,b1.x,b1.y,b1.z,b1.w};
#pragma unroll
            for (int i = 0; i < 8; i++)
#pragma unroll
                for (int j = 0; j < 8; j++) acc[i][j] += av[i] * bv[j];
        }
        __syncthreads();
    }
#pragma unroll
    for (int i = 0; i < 8; i++) {
        long row = bm + ty * 8 + i;
        float* crow = &C[row * (long)ldc + bn + tx * 8];
#pragma unroll
        for (int j = 0; j < 8; j++) {
            float v = acc[i][j];
            int col = bn + tx * 8 + j;
            if (bias1) v += bias1[col];
            if (bias2) v += bias2[col];
            if (ACCUM) v += crow[j];
            if (TANH)  v = tanhf(v);
            crow[j] = v;
        }
    }
}

__device__ __forceinline__ void gbar(unsigned bc) {
    __threadfence();
    __syncthreads();
    if (threadIdx.x == 0) {
        atomicAdd(&g_bar, 1u);
        unsigned target = bc * NB_LSTM;
        while (*((volatile unsigned*)&g_bar) < target) { __nanosleep(32); }
        __threadfence();
    }
    __syncthreads();
}

__global__ void reset_kernel() { g_bar = 0u; }

// 128 blocks = 2 dirs x 4 ntiles(512 cols) x 16 ksplits(32 k). w slice resident in smem.
__global__ void __launch_bounds__(512, 1) lstm_kernel(
    const float* __restrict__ whf, const float* __restrict__ whb)
{
    extern __shared__ float sm[];
    float (*ws)[512] = (float (*)[512])sm;              // [32][512]
    float (*hs)[64]  = (float (*)[64])(sm + 32 * 512);  // [32][64]
    int tid = threadIdx.x, bid = blockIdx.x;
    int dir = bid >> 6, b64 = bid & 63;
    int ntile = b64 >> 4, ks = b64 & 15;
    int n0 = ntile * 512, k0 = ks * 32;
    const float* W    = dir ? whb : whf;
    const float* xpre = dir ? g_xpre_b : g_xpre_f;

    for (int idx = tid; idx < 32 * 512; idx += 512) {
        int cc = idx >> 5, kk = idx & 31;
        ws[kk][cc] = W[(long)(n0 + cc) * H_ + k0 + kk];
    }
    __syncthreads();

    int u = b64 * 512 + tid;
    int ub = u >> 9, uj = u & 511;
    float c_reg = 0.f;
    int tx = tid & 63, ty = tid >> 6;
    unsigned bc = 0;

    for (int s = 0; s < T_; s++) {
        int t = dir ? (T_ - 1 - s) : s;
        if (s > 0) {
            int tp = dir ? (t + 1) : (t - 1);
            for (int idx = tid; idx < 2048; idx += 512) {
                int b = idx >> 5, kk = idx & 31;
                hs[kk][b] = __ldcg(&g_ctx[((long)b * T_ + tp) * D_ + dir * H_ + k0 + kk]);
            }
            __syncthreads();
            float acc[8][8];
#pragma unroll
            for (int i = 0; i < 8; i++)
#pragma unroll
                for (int j = 0; j < 8; j++) acc[i][j] = 0.f;
#pragma unroll 4
            for (int kk = 0; kk < 32; kk++) {
                float4 h0 = *(const float4*)&hs[kk][ty * 8];
                float4 h1 = *(const float4*)&hs[kk][ty * 8 + 4];
                float4 w0 = *(const float4*)&ws[kk][tx * 8];
                float4 w1 = *(const float4*)&ws[kk][tx * 8 + 4];
                float hv[8] = {h0.x,h0.y,h0.z,h0.w,h1.x,h1.y,h1.z,h1.w};
                float wv[8] = {w0.x,w0.y,w0.z,w0.w,w1.x,w1.y,w1.z,w1.w};
#pragma unroll
                for (int i = 0; i < 8; i++)
#pragma unroll
                    for (int j = 0; j < 8; j++) acc[i][j] += hv[i] * wv[j];
            }
            float* pp = &g_partial[((long)dir * 16 + ks) * B_ * G_];
#pragma unroll
            for (int i = 0; i < 8; i++) {
                long base = (long)(ty * 8 + i) * G_ + n0 + tx * 8;
                *(float4*)&pp[base]     = make_float4(acc[i][0],acc[i][1],acc[i][2],acc[i][3]);
                *(float4*)&pp[base + 4] = make_float4(acc[i][4],acc[i][5],acc[i][6],acc[i][7]);
            }
            __syncthreads();
        }
        gbar(++bc);

        {   // cell update: one (batch, hidden j) per thread
            const float* xp = &xpre[((long)ub * T_ + t) * G_];
            float gv[4];
#pragma unroll
            for (int g = 0; g < 4; g++) {
                int col = g * H_ + uj;
                float v = xp[col];
                if (s > 0) {
#pragma unroll
                    for (int sp = 0; sp < 16; sp++)
                        v += __ldcg(&g_partial[(((long)dir * 16 + sp) * B_ + ub) * G_ + col]);
                }
                gv[g] = v;
            }
            float ig = 1.f / (1.f + expf(-gv[0]));
            float fg = 1.f / (1.f + expf(-gv[1]));
            float gg = tanhf(gv[2]);
            float og = 1.f / (1.f + expf(-gv[3]));
            c_reg = fg * c_reg + ig * gg;
            g_ctx[((long)ub * T_ + t) * D_ + dir * H_ + uj] = og * tanhf(c_reg);
        }
        gbar(++bc);
    }
}

__global__ void softmax_kernel(const unsigned char* __restrict__ mask) {
    int row = blockIdx.x;          // b*T + q
    int tid = threadIdx.x;         // k
    int b = row >> 8;
    float v = g_scores[(long)row * T_ + tid];
    if (mask[b * T_ + tid]) v = -INFINITY;
    __shared__ float red[256];
    red[tid] = v; __syncthreads();
    for (int s = 128; s > 0; s >>= 1) {
        if (tid < s) red[tid] = fmaxf(red[tid], red[tid + s]);
        __syncthreads();
    }
    float m = red[0]; __syncthreads();
    float e = __expf(v - m);
    red[tid] = e; __syncthreads();
    for (int s = 128; s > 0; s >>= 1) {
        if (tid < s) red[tid] += red[tid + s];
        __syncthreads();
    }
    g_scores[(long)row * T_ + tid] = e / red[0];
}

__global__ void mean_kernel() {
    int idx = blockIdx.x * 256 + threadIdx.x;  // B*D
    int b = idx >> 10, d = idx & 1023;
    const float* p = &g_htilde[(long)b * T_ * D_ + d];
    float s = 0.f;
    for (int t = 0; t < T_; t++) s += p[(long)t * D_];
    g_ctxout[idx] = s * (1.0f / T_);
}

__global__ void yhead_kernel(const float* __restrict__ w_out, const float* __restrict__ b_out) {
    int m = blockIdx.x, tid = threadIdx.x;
    int wid = tid >> 5, lid = tid & 31;
    const float* x = &g_ctxout[m * D_];
    for (int n = wid; n < OUT_; n += 8) {
        const float* w = &w_out[(long)n * D_];
        float s = 0.f;
        for (int k = lid; k < D_; k += 32) s += x[k] * w[k];
#pragma unroll
        for (int o = 16; o > 0; o >>= 1) s += __shfl_down_sync(0xffffffffu, s, o);
        if (lid == 0) g_y[m * OUT_ + n] = tanhf(s + b_out[n]);
    }
}

__global__ void bn_kernel(const float* __restrict__ gamma, const float* __restrict__ beta,
                          float* __restrict__ out) {
    int n = threadIdx.x;
    float mu = 0.f;
    for (int b = 0; b < B_; b++) mu += g_y[b * OUT_ + n];
    mu *= (1.0f / B_);
    float var = 0.f;
    for (int b = 0; b < B_; b++) { float d = g_y[b * OUT_ + n] - mu; var += d * d; }
    var *= (1.0f / B_);
    float inv = rsqrtf(var + 1e-5f);
    float ga = gamma[n], be = beta[n];
    for (int b = 0; b < B_; b++)
        out[b * OUT_ + n] = ga * (g_y[b * OUT_ + n] - mu) * inv + be;
}

extern "C" void kernel_launch(void* const* d_in, const int* in_sizes, int n_in,
                              void* d_out, int out_size) {
    const int*   inputs = (const int*)d_in[0];
    const unsigned char* mask = (const unsigned char*)d_in[1];
    const float* table  = (const float*)d_in[2];
    const float* w_ih_f = (const float*)d_in[3];
    const float* w_hh_f = (const float*)d_in[4];
    const float* b_ih_f = (const float*)d_in[5];
    const float* b_hh_f = (const float*)d_in[6];
    const float* w_ih_b = (const float*)d_in[7];
    const float* w_hh_b = (const float*)d_in[8];
    const float* b_ih_b = (const float*)d_in[9];
    const float* b_hh_b = (const float*)d_in[10];
    const float* w_in   = (const float*)d_in[11];
    const float* w_attn = (const float*)d_in[12];
    const float* w_out  = (const float*)d_in[13];
    const float* b_out  = (const float*)d_in[14];
    const float* gamma  = (const float*)d_in[15];
    const float* beta   = (const float*)d_in[16];
    float* out = (float*)d_out;

    float *embeds, *xf, *xb, *ctx, *target, *scores, *weighted, *htilde;
    cudaGetSymbolAddress((void**)&embeds,   g_embeds);
    cudaGetSymbolAddress((void**)&xf,       g_xpre_f);
    cudaGetSymbolAddress((void**)&xb,       g_xpre_b);
    cudaGetSymbolAddress((void**)&ctx,      g_ctx);
    cudaGetSymbolAddress((void**)&target,   g_target);
    cudaGetSymbolAddress((void**)&scores,   g_scores);
    cudaGetSymbolAddress((void**)&weighted, g_weighted);
    cudaGetSymbolAddress((void**)&htilde,   g_htilde);

    // 1. embedding gather
    embed_kernel<<<(B_*T_*E_ + 255) / 256, 256>>>(inputs, table);

    // 2. input projections: xpre = embeds @ w_ih^T + b_ih + b_hh   [16384 x 2048]
    {
        dim3 g(G_/128, (B_*T_)/128, 1);
        gemm_kernel<true,false,false><<<g, 256>>>(embeds, w_ih_f, b_ih_f, b_hh_f, xf,
            B_*T_, G_, E_, E_, E_, G_, 0, 0, 0);
        gemm_kernel<true,false,false><<<g, 256>>>(embeds, w_ih_b, b_ih_b, b_hh_b, xb,
            B_*T_, G_, E_, E_, E_, G_, 0, 0, 0);
    }

    // 3. persistent bidirectional LSTM scan
    reset_kernel<<<1, 1>>>();
    {
        int smem = (32*512 + 32*64) * sizeof(float);
        cudaFuncSetAttribute(lstm_kernel, cudaFuncAttributeMaxDynamicSharedMemorySize, smem);
        lstm_kernel<<<NB_LSTM, 512, smem>>>(w_hh_f, w_hh_b);
    }

    // 4. target = ctx @ w_in^T   [16384 x 1024]
    {
        dim3 g(D_/128, (B_*T_)/128, 1);
        gemm_kernel<true,false,false><<<g, 256>>>(ctx, w_in, nullptr, nullptr, target,
            B_*T_, D_, D_, D_, D_, D_, 0, 0, 0);
    }

    // 5. scores[b] = target[b] @ ctx[b]^T   batched [256 x 256 x 1024]
    {
        dim3 g(T_/128, T_/128, B_);
        gemm_kernel<true,false,false><<<g, 256>>>(target, ctx, nullptr, nullptr, scores,
            T_, T_, D_, D_, D_, T_, (long)T_*D_, (long)T_*D_, (long)T_*T_);
    }

    // 6. masked softmax (in-place on scores)
    softmax_kernel<<<B_*T_, 256>>>(mask);

    // 7. weighted[b] = attn[b] @ ctx[b]   batched [256 x 1024 x 256]
    {
        dim3 g(D_/128, T_/128, B_);
        gemm_kernel<false,false,false><<<g, 256>>>(scores, ctx, nullptr, nullptr, weighted,
            T_, D_, T_, T_, D_, D_, (long)T_*T_, (long)T_*D_, (long)T_*D_);
    }

    // 8. h_tilde = tanh(weighted @ W1^T + ctx @ W2^T)   W = w_out_attn [1024 x 2048]
    {
        dim3 g(D_/128, (B_*T_)/128, 1);
        gemm_kernel<true,false,false><<<g, 256>>>(weighted, w_attn, nullptr, nullptr, htilde,
            B_*T_, D_, D_, D_, 2*D_, D_, 0, 0, 0);
        gemm_kernel<true,true,true><<<g, 256>>>(ctx, w_attn + D_, nullptr, nullptr, htilde,
            B_*T_, D_, D_, D_, 2*D_, D_, 0, 0, 0);
    }

    // 9-11. mean over T, output head, batchnorm
    mean_kernel<<<(B_*D_)/256, 256>>>();
    yhead_kernel<<<B_, 256>>>(w_out, b_out);
    bn_kernel<<<1, OUT_>>>(gamma, beta, out);
}

// round 9
// speedup vs baseline: 2.7888x; 2.7888x over previous
#include <cuda_runtime.h>
#include <cuda_bf16.h>
#include <cstdint>
#include <math.h>

#define B_   64
#define T_   256
#define E_   300
#define EP_  320
#define H_   512
#define D_   1024
#define G_   2048
#define OUT_ 256
#define NB_LSTM 128u
#define BT_  (B_*T_)

// ---------------- fp32 scratch ----------------
__device__ float g_embeds[BT_*E_];
__device__ float g_xpre_f[BT_*G_];
__device__ float g_xpre_b[BT_*G_];
__device__ float g_ctx[BT_*D_];
__device__ float g_scores[BT_*T_];
__device__ float g_htilde[BT_*D_];
__device__ float g_partial[2*16*B_*G_];
__device__ float g_ctxout[B_*D_];
__device__ float g_y[B_*OUT_];
__device__ float g_bsum_f[G_];
__device__ float g_bsum_b[G_];
__device__ unsigned g_bar;

// ---------------- bf16 hi/lo scratch (16B aligned) ----------------
__device__ __align__(16) __nv_bfloat16 g_eh[BT_*EP_],   g_el[BT_*EP_];
__device__ __align__(16) __nv_bfloat16 g_wfh[G_*EP_],   g_wfl[G_*EP_];
__device__ __align__(16) __nv_bfloat16 g_wbh[G_*EP_],   g_wbl[G_*EP_];
__device__ __align__(16) __nv_bfloat16 g_ch[BT_*D_],    g_cl[BT_*D_];
__device__ __align__(16) __nv_bfloat16 g_cth[B_*D_*T_], g_ctl[B_*D_*T_];
__device__ __align__(16) __nv_bfloat16 g_winh[D_*D_],   g_winl[D_*D_];
__device__ __align__(16) __nv_bfloat16 g_th[BT_*D_],    g_tl[BT_*D_];
__device__ __align__(16) __nv_bfloat16 g_ah[BT_*T_],    g_al[BT_*T_];
__device__ __align__(16) __nv_bfloat16 g_w1h[D_*D_],    g_w1l[D_*D_];
__device__ __align__(16) __nv_bfloat16 g_w2h[D_*D_],    g_w2l[D_*D_];
__device__ __align__(16) __nv_bfloat16 g_wh[BT_*D_],    g_wl[BT_*D_];

// ---------------- embedding ----------------
__global__ void embed_kernel(const int* __restrict__ inp, const float* __restrict__ table) {
    int idx = blockIdx.x * blockDim.x + threadIdx.x;
    if (idx >= BT_*E_) return;
    int bt = idx / E_, e = idx - bt * E_;
    g_embeds[idx] = table[(long)inp[bt] * E_ + e];
}

// ---------------- fp32 -> bf16 hi/lo split (with K pad) ----------------
__global__ void conv_kernel(const float* __restrict__ src, __nv_bfloat16* __restrict__ hi,
                            __nv_bfloat16* __restrict__ lo, int rows, int scols, int sld, int dld) {
    long idx = (long)blockIdx.x * 256 + threadIdx.x;
    if (idx >= (long)rows * dld) return;
    int r = idx / dld, c = idx - (long)r * dld;
    float v = (c < scols) ? src[(long)r * sld + c] : 0.f;
    __nv_bfloat16 h = __float2bfloat16(v);
    hi[idx] = h;
    lo[idx] = __float2bfloat16(v - __bfloat162float(h));
}

// ---------------- ctx transpose + split: [b][t][d] -> [b][d][t] ----------------
__global__ void tconv_kernel(const float* __restrict__ src, __nv_bfloat16* __restrict__ hi,
                             __nv_bfloat16* __restrict__ lo) {
    __shared__ float tile[32][33];
    int z = blockIdx.z, t0 = blockIdx.x * 32, d0 = blockIdx.y * 32;
    int tx = threadIdx.x, ty = threadIdx.y;
#pragma unroll
    for (int i = 0; i < 4; i++)
        tile[ty + i*8][tx] = src[((long)z*T_ + t0 + ty + i*8) * D_ + d0 + tx];
    __syncthreads();
#pragma unroll
    for (int i = 0; i < 4; i++) {
        float v = tile[tx][ty + i*8];
        long o = ((long)z*D_ + d0 + ty + i*8) * T_ + t0 + tx;
        __nv_bfloat16 h = __float2bfloat16(v);
        hi[o] = h; lo[o] = __float2bfloat16(v - __bfloat162float(h));
    }
}

__global__ void bsum_kernel(const float* a, const float* b, const float* a2, const float* b2) {
    int i = blockIdx.x * 256 + threadIdx.x;
    if (i < G_) { g_bsum_f[i] = a[i] + b[i]; g_bsum_b[i] = a2[i] + b2[i]; }
}

// ---------------- split-bf16 tensor-core GEMM (mma.sync, baseline PTX) ----------------
// D[m][n] = sum_k A[m,k]*B[n,k], accumulated over up to 2 (A,B,K) operand pairs.
struct GemmP {
    const __nv_bfloat16 *Ah[2], *Al[2], *Bh[2], *Bl[2];
    int K[2], lda[2], ldb[2];
    long sA[2], sB[2];
    int nt;
    float* C; int ldc; long sC;
    const float* bias;
    __nv_bfloat16 *Chi, *Clo; int ldhl; long sHL;
};

#define SROW   40                  // smem row stride in bf16 (conflict-free)
#define TILEB  (128*SROW*2)        // 10240 B per tile
#define STAGEB (4*TILEB)           // Ah,Al,Bh,Bl
#define GEMM_SMEM (2*STAGEB)       // double buffer: 81920 B

__device__ __forceinline__ uint32_t smem_u32_of(const void* p) {
    uint32_t a;
    asm("{ .reg .u64 t; cvta.to.shared.u64 t, %1; cvt.u32.u64 %0, t; }" : "=r"(a) : "l"(p));
    return a;
}
__device__ __forceinline__ void cpasync16(uint32_t s, const void* g) {
    asm volatile("cp.async.cg.shared.global [%0], [%1], 16;" :: "r"(s), "l"(g));
}
__device__ __forceinline__ void cpcommit() { asm volatile("cp.async.commit_group;"); }
template<int N> __device__ __forceinline__ void cpwait() {
    asm volatile("cp.async.wait_group %0;" :: "n"(N));
}

#define MMA16816(d, a, b0v, b1v) \
    asm volatile("mma.sync.aligned.m16n8k16.row.col.f32.bf16.bf16.f32 " \
        "{%0,%1,%2,%3}, {%4,%5,%6,%7}, {%8,%9}, {%0,%1,%2,%3};" \
        : "+f"((d)[0]), "+f"((d)[1]), "+f"((d)[2]), "+f"((d)[3]) \
        : "r"((a)[0]), "r"((a)[1]), "r"((a)[2]), "r"((a)[3]), "r"(b0v), "r"(b1v))

__device__ __forceinline__ void issue_stage(
    const GemmP& P, int z, int c, int nc0, int buf,
    int tid, int bm, int bn, uint32_t sbase)
{
    int t  = (c < nc0) ? 0 : 1;
    int ch = (c < nc0) ? c : (c - nc0);
    const __nv_bfloat16* Ah = P.Ah[t] + (long)z * P.sA[t];
    const __nv_bfloat16* Al = P.Al[t] + (long)z * P.sA[t];
    const __nv_bfloat16* Bh = P.Bh[t] + (long)z * P.sB[t];
    const __nv_bfloat16* Bl = P.Bl[t] + (long)z * P.sB[t];
    int lda = P.lda[t], ldb = P.ldb[t];
    int kb0 = ch * 32;
#pragma unroll
    for (int i = 0; i < 8; i++) {
        int idx  = i * 256 + tid;           // 0..2047
        int tile = idx >> 9;                // 0..3
        int cc   = idx & 511;               // chunk within tile
        int row  = cc >> 2;                 // 0..127
        int seg  = cc & 3;                  // 16B segment (8 bf16)
        uint32_t sa = sbase + buf * STAGEB + tile * TILEB + (row * SROW + seg * 8) * 2;
        int kb = kb0 + seg * 8;
        const __nv_bfloat16* src;
        if      (tile == 0) src = Ah + (long)(bm + row) * lda + kb;
        else if (tile == 1) src = Al + (long)(bm + row) * lda + kb;
        else if (tile == 2) src = Bh + (long)(bn + row) * ldb + kb;
        else                src = Bl + (long)(bn + row) * ldb + kb;
        cpasync16(sa, src);
    }
    cpcommit();
}

template<bool TANH, bool WF32, bool WBF16>
__global__ void __launch_bounds__(256, 2) mma_gemm_kernel(GemmP P) {
    extern __shared__ __align__(16) char smem[];
    const int tid = threadIdx.x, lane = tid & 31, wid = tid >> 5;
    const int g = lane >> 2, tg = lane & 3;
    const int wm = (wid & 3) * 32, wn = (wid >> 2) * 64;
    const int bn = blockIdx.x * 128, bm = blockIdx.y * 128, z = blockIdx.z;
    const uint32_t sbase = smem_u32_of(smem);

    float acc[2][8][4];
#pragma unroll
    for (int mt = 0; mt < 2; mt++)
#pragma unroll
        for (int nt = 0; nt < 8; nt++)
#pragma unroll
            for (int r = 0; r < 4; r++) acc[mt][nt][r] = 0.f;

    const int nc0 = P.K[0] >> 5;
    const int nct = nc0 + ((P.nt > 1) ? (P.K[1] >> 5) : 0);

    issue_stage(P, z, 0, nc0, 0, tid, bm, bn, sbase);

    for (int c = 0; c < nct; c++) {
        int buf = c & 1;
        if (c + 1 < nct) { issue_stage(P, z, c + 1, nc0, buf ^ 1, tid, bm, bn, sbase); cpwait<1>(); }
        else             { cpwait<0>(); }
        __syncthreads();

        const __nv_bfloat16* Ash = (const __nv_bfloat16*)(smem + buf * STAGEB);
        const __nv_bfloat16* Asl = Ash + 128 * SROW;
        const __nv_bfloat16* Bsh = Asl + 128 * SROW;
        const __nv_bfloat16* Bsl = Bsh + 128 * SROW;

#pragma unroll
        for (int s = 0; s < 2; s++) {
            int k0 = s * 16;
            uint32_t ah[2][4], al[2][4];
#pragma unroll
            for (int mt = 0; mt < 2; mt++) {
                int r = wm + mt * 16 + g;
                ah[mt][0] = *(const uint32_t*)&Ash[(r    ) * SROW + k0     + tg * 2];
                ah[mt][1] = *(const uint32_t*)&Ash[(r + 8) * SROW + k0     + tg * 2];
                ah[mt][2] = *(const uint32_t*)&Ash[(r    ) * SROW + k0 + 8 + tg * 2];
                ah[mt][3] = *(const uint32_t*)&Ash[(r + 8) * SROW + k0 + 8 + tg * 2];
                al[mt][0] = *(const uint32_t*)&Asl[(r    ) * SROW + k0     + tg * 2];
                al[mt][1] = *(const uint32_t*)&Asl[(r + 8) * SROW + k0     + tg * 2];
                al[mt][2] = *(const uint32_t*)&Asl[(r    ) * SROW + k0 + 8 + tg * 2];
                al[mt][3] = *(const uint32_t*)&Asl[(r + 8) * SROW + k0 + 8 + tg * 2];
            }
#pragma unroll
            for (int nt = 0; nt < 8; nt++) {
                int n = wn + nt * 8 + g;
                uint32_t bh0 = *(const uint32_t*)&Bsh[n * SROW + k0     + tg * 2];
                uint32_t bh1 = *(const uint32_t*)&Bsh[n * SROW + k0 + 8 + tg * 2];
                uint32_t bl0 = *(const uint32_t*)&Bsl[n * SROW + k0     + tg * 2];
                uint32_t bl1 = *(const uint32_t*)&Bsl[n * SROW + k0 + 8 + tg * 2];
#pragma unroll
                for (int mt = 0; mt < 2; mt++) {
                    MMA16816(acc[mt][nt], ah[mt], bh0, bh1);
                    MMA16816(acc[mt][nt], ah[mt], bl0, bl1);
                    MMA16816(acc[mt][nt], al[mt], bh0, bh1);
                }
            }
        }
        __syncthreads();
    }

    // epilogue from registers
#pragma unroll
    for (int mt = 0; mt < 2; mt++) {
#pragma unroll
        for (int nt = 0; nt < 8; nt++) {
            int col = bn + wn + nt * 8 + tg * 2;
            float bv0 = P.bias ? P.bias[col]     : 0.f;
            float bv1 = P.bias ? P.bias[col + 1] : 0.f;
#pragma unroll
            for (int h = 0; h < 2; h++) {
                int row = bm + wm + mt * 16 + g + h * 8;
                float v0 = acc[mt][nt][h * 2]     + bv0;
                float v1 = acc[mt][nt][h * 2 + 1] + bv1;
                if (TANH) { v0 = tanhf(v0); v1 = tanhf(v1); }
                if (WF32) {
                    float* cp = P.C + (long)z * P.sC + (long)row * P.ldc + col;
                    cp[0] = v0; cp[1] = v1;
                }
                if (WBF16) {
                    long o = (long)z * P.sHL + (long)row * P.ldhl + col;
                    __nv_bfloat16 h0 = __float2bfloat16(v0);
                    __nv_bfloat16 h1 = __float2bfloat16(v1);
                    P.Chi[o] = h0; P.Chi[o + 1] = h1;
                    P.Clo[o]     = __float2bfloat16(v0 - __bfloat162float(h0));
                    P.Clo[o + 1] = __float2bfloat16(v1 - __bfloat162float(h1));
                }
            }
        }
    }
}

// ---------------- persistent bidirectional LSTM (unchanged from passing R5) ----------------
__device__ __forceinline__ void gbar(unsigned bc) {
    __threadfence();
    __syncthreads();
    if (threadIdx.x == 0) {
        atomicAdd(&g_bar, 1u);
        unsigned target = bc * NB_LSTM;
        while (*((volatile unsigned*)&g_bar) < target) { __nanosleep(32); }
        __threadfence();
    }
    __syncthreads();
}
__global__ void reset_kernel() { g_bar = 0u; }

__global__ void __launch_bounds__(512, 1) lstm_kernel(
    const float* __restrict__ whf, const float* __restrict__ whb)
{
    extern __shared__ float sm[];
    float (*ws)[512] = (float (*)[512])sm;
    float (*hs)[64]  = (float (*)[64])(sm + 32 * 512);
    int tid = threadIdx.x, bid = blockIdx.x;
    int dir = bid >> 6, b64 = bid & 63;
    int ntile = b64 >> 4, ks = b64 & 15;
    int n0 = ntile * 512, k0 = ks * 32;
    const float* W    = dir ? whb : whf;
    const float* xpre = dir ? g_xpre_b : g_xpre_f;

    for (int idx = tid; idx < 32 * 512; idx += 512) {
        int cc = idx >> 5, kk = idx & 31;
        ws[kk][cc] = W[(long)(n0 + cc) * H_ + k0 + kk];
    }
    __syncthreads();

    int u = b64 * 512 + tid;
    int ub = u >> 9, uj = u & 511;
    float c_reg = 0.f;
    int tx = tid & 63, ty = tid >> 6;
    unsigned bc = 0;

    for (int s = 0; s < T_; s++) {
        int t = dir ? (T_ - 1 - s) : s;
        if (s > 0) {
            int tp = dir ? (t + 1) : (t - 1);
            for (int idx = tid; idx < 2048; idx += 512) {
                int b = idx >> 5, kk = idx & 31;
                hs[kk][b] = __ldcg(&g_ctx[((long)b * T_ + tp) * D_ + dir * H_ + k0 + kk]);
            }
            __syncthreads();
            float acc[8][8];
#pragma unroll
            for (int i = 0; i < 8; i++)
#pragma unroll
                for (int j = 0; j < 8; j++) acc[i][j] = 0.f;
#pragma unroll 4
            for (int kk = 0; kk < 32; kk++) {
                float4 h0 = *(const float4*)&hs[kk][ty * 8];
                float4 h1 = *(const float4*)&hs[kk][ty * 8 + 4];
                float4 w0 = *(const float4*)&ws[kk][tx * 8];
                float4 w1 = *(const float4*)&ws[kk][tx * 8 + 4];
                float hv[8] = {h0.x,h0.y,h0.z,h0.w,h1.x,h1.y,h1.z,h1.w};
                float wv[8] = {w0.x,w0.y,w0.z,w0.w,w1.x,w1.y,w1.z,w1.w};
#pragma unroll
                for (int i = 0; i < 8; i++)
#pragma unroll
                    for (int j = 0; j < 8; j++) acc[i][j] += hv[i] * wv[j];
            }
            float* pp = &g_partial[((long)dir * 16 + ks) * B_ * G_];
#pragma unroll
            for (int i = 0; i < 8; i++) {
                long base = (long)(ty * 8 + i) * G_ + n0 + tx * 8;
                *(float4*)&pp[base]     = make_float4(acc[i][0],acc[i][1],acc[i][2],acc[i][3]);
                *(float4*)&pp[base + 4] = make_float4(acc[i][4],acc[i][5],acc[i][6],acc[i][7]);
            }
            __syncthreads();
        }
        gbar(++bc);
        {
            const float* xp = &xpre[((long)ub * T_ + t) * G_];
            float gv[4];
#pragma unroll
            for (int g = 0; g < 4; g++) {
                int col = g * H_ + uj;
                float v = xp[col];
                if (s > 0) {
#pragma unroll
                    for (int sp = 0; sp < 16; sp++)
                        v += __ldcg(&g_partial[(((long)dir * 16 + sp) * B_ + ub) * G_ + col]);
                }
                gv[g] = v;
            }
            float ig = 1.f / (1.f + expf(-gv[0]));
            float fg = 1.f / (1.f + expf(-gv[1]));
            float gg = tanhf(gv[2]);
            float og = 1.f / (1.f + expf(-gv[3]));
            c_reg = fg * c_reg + ig * gg;
            g_ctx[((long)ub * T_ + t) * D_ + dir * H_ + uj] = og * tanhf(c_reg);
        }
        gbar(++bc);
    }
}

// ---------------- softmax / mean / head / bn ----------------
__global__ void softmax_kernel(const unsigned char* __restrict__ mask) {
    int row = blockIdx.x;
    int tid = threadIdx.x;
    int b = row >> 8;
    float v = g_scores[(long)row * T_ + tid];
    if (mask[b * T_ + tid]) v = -INFINITY;
    __shared__ float red[256];
    red[tid] = v; __syncthreads();
    for (int s = 128; s > 0; s >>= 1) {
        if (tid < s) red[tid] = fmaxf(red[tid], red[tid + s]);
        __syncthreads();
    }
    float m = red[0]; __syncthreads();
    float e = __expf(v - m);
    red[tid] = e; __syncthreads();
    for (int s = 128; s > 0; s >>= 1) {
        if (tid < s) red[tid] += red[tid + s];
        __syncthreads();
    }
    g_scores[(long)row * T_ + tid] = e / red[0];
}

__global__ void mean_kernel() {
    int idx = blockIdx.x * 256 + threadIdx.x;
    int b = idx >> 10, d = idx & 1023;
    const float* p = &g_htilde[(long)b * T_ * D_ + d];
    float s = 0.f;
    for (int t = 0; t < T_; t++) s += p[(long)t * D_];
    g_ctxout[idx] = s * (1.0f / T_);
}

__global__ void yhead_kernel(const float* __restrict__ w_out, const float* __restrict__ b_out) {
    int m = blockIdx.x, tid = threadIdx.x;
    int wid = tid >> 5, lid = tid & 31;
    const float* x = &g_ctxout[m * D_];
    for (int n = wid; n < OUT_; n += 8) {
        const float* w = &w_out[(long)n * D_];
        float s = 0.f;
        for (int k = lid; k < D_; k += 32) s += x[k] * w[k];
#pragma unroll
        for (int o = 16; o > 0; o >>= 1) s += __shfl_down_sync(0xffffffffu, s, o);
        if (lid == 0) g_y[m * OUT_ + n] = tanhf(s + b_out[n]);
    }
}

__global__ void bn_kernel(const float* __restrict__ gamma, const float* __restrict__ beta,
                          float* __restrict__ out) {
    int n = threadIdx.x;
    float mu = 0.f;
    for (int b = 0; b < B_; b++) mu += g_y[b * OUT_ + n];
    mu *= (1.0f / B_);
    float var = 0.f;
    for (int b = 0; b < B_; b++) { float d = g_y[b * OUT_ + n] - mu; var += d * d; }
    var *= (1.0f / B_);
    float inv = rsqrtf(var + 1e-5f);
    float ga = gamma[n], be = beta[n];
    for (int b = 0; b < B_; b++)
        out[b * OUT_ + n] = ga * (g_y[b * OUT_ + n] - mu) * inv + be;
}

// ---------------- host launcher ----------------
static inline void conv(const float* s, __nv_bfloat16* h, __nv_bfloat16* l,
                        int rows, int scols, int sld, int dld) {
    long tot = (long)rows * dld;
    conv_kernel<<<(unsigned)((tot + 255) / 256), 256>>>(s, h, l, rows, scols, sld, dld);
}

extern "C" void kernel_launch(void* const* d_in, const int* in_sizes, int n_in,
                              void* d_out, int out_size) {
    const int*   inputs = (const int*)d_in[0];
    const unsigned char* mask = (const unsigned char*)d_in[1];
    const float* table  = (const float*)d_in[2];
    const float* w_ih_f = (const float*)d_in[3];
    const float* w_hh_f = (const float*)d_in[4];
    const float* b_ih_f = (const float*)d_in[5];
    const float* b_hh_f = (const float*)d_in[6];
    const float* w_ih_b = (const float*)d_in[7];
    const float* w_hh_b = (const float*)d_in[8];
    const float* b_ih_b = (const float*)d_in[9];
    const float* b_hh_b = (const float*)d_in[10];
    const float* w_in   = (const float*)d_in[11];
    const float* w_attn = (const float*)d_in[12];
    const float* w_out  = (const float*)d_in[13];
    const float* b_out  = (const float*)d_in[14];
    const float* gamma  = (const float*)d_in[15];
    const float* beta   = (const float*)d_in[16];
    float* out = (float*)d_out;

    float *embeds, *xf, *xb, *ctx, *scores, *htilde, *bsf, *bsb;
    cudaGetSymbolAddress((void**)&embeds, g_embeds);
    cudaGetSymbolAddress((void**)&xf,     g_xpre_f);
    cudaGetSymbolAddress((void**)&xb,     g_xpre_b);
    cudaGetSymbolAddress((void**)&ctx,    g_ctx);
    cudaGetSymbolAddress((void**)&scores, g_scores);
    cudaGetSymbolAddress((void**)&htilde, g_htilde);
    cudaGetSymbolAddress((void**)&bsf,    g_bsum_f);
    cudaGetSymbolAddress((void**)&bsb,    g_bsum_b);
    __nv_bfloat16 *eh,*el,*wfh,*wfl,*wbh,*wbl,*ch,*cl,*cth,*ctl,*winh,*winl,
                  *th,*tl,*ah,*al,*w1h,*w1l,*w2h,*w2l,*wh,*wl;
    cudaGetSymbolAddress((void**)&eh, g_eh);   cudaGetSymbolAddress((void**)&el, g_el);
    cudaGetSymbolAddress((void**)&wfh, g_wfh); cudaGetSymbolAddress((void**)&wfl, g_wfl);
    cudaGetSymbolAddress((void**)&wbh, g_wbh); cudaGetSymbolAddress((void**)&wbl, g_wbl);
    cudaGetSymbolAddress((void**)&ch, g_ch);   cudaGetSymbolAddress((void**)&cl, g_cl);
    cudaGetSymbolAddress((void**)&cth, g_cth); cudaGetSymbolAddress((void**)&ctl, g_ctl);
    cudaGetSymbolAddress((void**)&winh, g_winh); cudaGetSymbolAddress((void**)&winl, g_winl);
    cudaGetSymbolAddress((void**)&th, g_th);   cudaGetSymbolAddress((void**)&tl, g_tl);
    cudaGetSymbolAddress((void**)&ah, g_ah);   cudaGetSymbolAddress((void**)&al, g_al);
    cudaGetSymbolAddress((void**)&w1h, g_w1h); cudaGetSymbolAddress((void**)&w1l, g_w1l);
    cudaGetSymbolAddress((void**)&w2h, g_w2h); cudaGetSymbolAddress((void**)&w2l, g_w2l);
    cudaGetSymbolAddress((void**)&wh, g_wh);   cudaGetSymbolAddress((void**)&wl, g_wl);

    cudaFuncSetAttribute(mma_gemm_kernel<false,true,false>,
                         cudaFuncAttributeMaxDynamicSharedMemorySize, GEMM_SMEM);
    cudaFuncSetAttribute(mma_gemm_kernel<false,false,true>,
                         cudaFuncAttributeMaxDynamicSharedMemorySize, GEMM_SMEM);
    cudaFuncSetAttribute(mma_gemm_kernel<true,true,false>,
                         cudaFuncAttributeMaxDynamicSharedMemorySize, GEMM_SMEM);

    // 1. embed + operand conversions
    embed_kernel<<<(BT_*E_ + 255) / 256, 256>>>(inputs, table);
    conv(embeds, eh, el, BT_, E_, E_, EP_);
    conv(w_ih_f, wfh, wfl, G_, E_, E_, EP_);
    conv(w_ih_b, wbh, wbl, G_, E_, E_, EP_);
    conv(w_in,   winh, winl, D_, D_, D_, D_);
    conv(w_attn,        w1h, w1l, D_, D_, 2*D_, D_);
    conv(w_attn + D_,   w2h, w2l, D_, D_, 2*D_, D_);
    bsum_kernel<<<(G_ + 255) / 256, 256>>>(b_ih_f, b_hh_f, b_ih_b, b_hh_b);

    // 2. xpre = embeds @ w_ih^T + (b_ih + b_hh)
    {
        GemmP P{};
        P.nt = 1; P.K[0] = EP_; P.lda[0] = EP_; P.ldb[0] = EP_;
        P.Ah[0] = eh; P.Al[0] = el; P.ldc = G_;
        P.Bh[0] = wfh; P.Bl[0] = wfl; P.C = xf; P.bias = bsf;
        dim3 g(G_/128, BT_/128, 1);
        mma_gemm_kernel<false,true,false><<<g, 256, GEMM_SMEM>>>(P);
        P.Bh[0] = wbh; P.Bl[0] = wbl; P.C = xb; P.bias = bsb;
        mma_gemm_kernel<false,true,false><<<g, 256, GEMM_SMEM>>>(P);
    }

    // 3. persistent bidirectional LSTM
    reset_kernel<<<1, 1>>>();
    {
        int smem = (32*512 + 32*64) * sizeof(float);
        cudaFuncSetAttribute(lstm_kernel, cudaFuncAttributeMaxDynamicSharedMemorySize, smem);
        lstm_kernel<<<NB_LSTM, 512, smem>>>(w_hh_f, w_hh_b);
    }

    // 4. ctx conversions
    conv(ctx, ch, cl, BT_, D_, D_, D_);
    tconv_kernel<<<dim3(T_/32, D_/32, B_), dim3(32, 8)>>>(ctx, cth, ctl);

    // 5. target = ctx @ w_in^T  (bf16 hi/lo out)
    {
        GemmP P{};
        P.nt = 1; P.K[0] = D_; P.lda[0] = D_; P.ldb[0] = D_;
        P.Ah[0] = ch; P.Al[0] = cl; P.Bh[0] = winh; P.Bl[0] = winl;
        P.Chi = th; P.Clo = tl; P.ldhl = D_;
        dim3 g(D_/128, BT_/128, 1);
        mma_gemm_kernel<false,false,true><<<g, 256, GEMM_SMEM>>>(P);
    }

    // 6. scores[z] = target[z] @ ctx[z]^T  (fp32 out)
    {
        GemmP P{};
        P.nt = 1; P.K[0] = D_; P.lda[0] = D_; P.ldb[0] = D_;
        P.Ah[0] = th; P.Al[0] = tl; P.sA[0] = (long)T_*D_;
        P.Bh[0] = ch; P.Bl[0] = cl; P.sB[0] = (long)T_*D_;
        P.C = scores; P.ldc = T_; P.sC = (long)T_*T_;
        dim3 g(T_/128, T_/128, B_);
        mma_gemm_kernel<false,true,false><<<g, 256, GEMM_SMEM>>>(P);
    }

    // 7. softmax + attn split
    softmax_kernel<<<BT_, 256>>>(mask);
    conv(scores, ah, al, BT_, T_, T_, T_);

    // 8. weighted[z] = attn[z] @ ctxT[z]^T  (bf16 hi/lo out)
    {
        GemmP P{};
        P.nt = 1; P.K[0] = T_; P.lda[0] = T_; P.ldb[0] = T_;
        P.Ah[0] = ah; P.Al[0] = al; P.sA[0] = (long)T_*T_;
        P.Bh[0] = cth; P.Bl[0] = ctl; P.sB[0] = (long)D_*T_;
        P.Chi = wh; P.Clo = wl; P.ldhl = D_; P.sHL = (long)T_*D_;
        dim3 g(D_/128, T_/128, B_);
        mma_gemm_kernel<false,false,true><<<g, 256, GEMM_SMEM>>>(P);
    }

    // 9. htilde = tanh(weighted @ W1^T + ctx @ W2^T)
    {
        GemmP P{};
        P.nt = 2;
        P.K[0] = D_; P.lda[0] = D_; P.ldb[0] = D_;
        P.Ah[0] = wh; P.Al[0] = wl; P.Bh[0] = w1h; P.Bl[0] = w1l;
        P.K[1] = D_; P.lda[1] = D_; P.ldb[1] = D_;
        P.Ah[1] = ch; P.Al[1] = cl; P.Bh[1] = w2h; P.Bl[1] = w2l;
        P.C = htilde; P.ldc = D_;
        dim3 g(D_/128, BT_/128, 1);
        mma_gemm_kernel<true,true,false><<<g, 256, GEMM_SMEM>>>(P);
    }

    // 10-12. mean, head, batchnorm
    mean_kernel<<<(B_*D_)/256, 256>>>();
    yhead_kernel<<<B_, 256>>>(w_out, b_out);
    bn_kernel<<<1, OUT_>>>(gamma, beta, out);
}

// round 11
// speedup vs baseline: 3.9522x; 1.4172x over previous
#include <cuda_runtime.h>
#include <cuda_bf16.h>
#include <cstdint>
#include <math.h>

#define B_   64
#define T_   256
#define E_   300
#define EP_  320
#define H_   512
#define D_   1024
#define G_   2048
#define OUT_ 256
#define NB_LSTM 128u
#define BT_  (B_*T_)

// ---------------- fp32 scratch ----------------
__device__ float g_embeds[BT_*E_];
__device__ float g_xpre_f[BT_*G_];
__device__ float g_xpre_b[BT_*G_];
__device__ float g_ctx[BT_*D_];
__device__ float g_scores[BT_*T_];
__device__ float g_htilde[BT_*D_];
__device__ float g_ctxout[B_*D_];
__device__ float g_y[B_*OUT_];
__device__ float g_bsum_f[G_];
__device__ float g_bsum_b[G_];
__device__ unsigned g_bar;

// LSTM recurrent h, split bf16, double-buffered: [dir][buf][64*512]
__device__ __align__(16) __nv_bfloat16 g_hhi[2][2][B_*H_];
__device__ __align__(16) __nv_bfloat16 g_hlo[2][2][B_*H_];

// ---------------- bf16 hi/lo scratch (16B aligned) ----------------
__device__ __align__(16) __nv_bfloat16 g_eh[BT_*EP_],   g_el[BT_*EP_];
__device__ __align__(16) __nv_bfloat16 g_wfh[G_*EP_],   g_wfl[G_*EP_];
__device__ __align__(16) __nv_bfloat16 g_wbh[G_*EP_],   g_wbl[G_*EP_];
__device__ __align__(16) __nv_bfloat16 g_ch[BT_*D_],    g_cl[BT_*D_];
__device__ __align__(16) __nv_bfloat16 g_cth[B_*D_*T_], g_ctl[B_*D_*T_];
__device__ __align__(16) __nv_bfloat16 g_winh[D_*D_],   g_winl[D_*D_];
__device__ __align__(16) __nv_bfloat16 g_th[BT_*D_],    g_tl[BT_*D_];
__device__ __align__(16) __nv_bfloat16 g_ah[BT_*T_],    g_al[BT_*T_];
__device__ __align__(16) __nv_bfloat16 g_w1h[D_*D_],    g_w1l[D_*D_];
__device__ __align__(16) __nv_bfloat16 g_w2h[D_*D_],    g_w2l[D_*D_];
__device__ __align__(16) __nv_bfloat16 g_wh[BT_*D_],    g_wl[BT_*D_];

// ---------------- embedding ----------------
__global__ void embed_kernel(const int* __restrict__ inp, const float* __restrict__ table) {
    int idx = blockIdx.x * blockDim.x + threadIdx.x;
    if (idx >= BT_*E_) return;
    int bt = idx / E_, e = idx - bt * E_;
    g_embeds[idx] = table[(long)inp[bt] * E_ + e];
}

// ---------------- fp32 -> bf16 hi/lo split (with K pad) ----------------
__global__ void conv_kernel(const float* __restrict__ src, __nv_bfloat16* __restrict__ hi,
                            __nv_bfloat16* __restrict__ lo, int rows, int scols, int sld, int dld) {
    long idx = (long)blockIdx.x * 256 + threadIdx.x;
    if (idx >= (long)rows * dld) return;
    int r = idx / dld, c = idx - (long)r * dld;
    float v = (c < scols) ? src[(long)r * sld + c] : 0.f;
    __nv_bfloat16 h = __float2bfloat16(v);
    hi[idx] = h;
    lo[idx] = __float2bfloat16(v - __bfloat162float(h));
}

// ---------------- ctx transpose + split: [b][t][d] -> [b][d][t] ----------------
__global__ void tconv_kernel(const float* __restrict__ src, __nv_bfloat16* __restrict__ hi,
                             __nv_bfloat16* __restrict__ lo) {
    __shared__ float tile[32][33];
    int z = blockIdx.z, t0 = blockIdx.x * 32, d0 = blockIdx.y * 32;
    int tx = threadIdx.x, ty = threadIdx.y;
#pragma unroll
    for (int i = 0; i < 4; i++)
        tile[ty + i*8][tx] = src[((long)z*T_ + t0 + ty + i*8) * D_ + d0 + tx];
    __syncthreads();
#pragma unroll
    for (int i = 0; i < 4; i++) {
        float v = tile[tx][ty + i*8];
        long o = ((long)z*D_ + d0 + ty + i*8) * T_ + t0 + tx;
        __nv_bfloat16 h = __float2bfloat16(v);
        hi[o] = h; lo[o] = __float2bfloat16(v - __bfloat162float(h));
    }
}

__global__ void bsum_kernel(const float* a, const float* b, const float* a2, const float* b2) {
    int i = blockIdx.x * 256 + threadIdx.x;
    if (i < G_) { g_bsum_f[i] = a[i] + b[i]; g_bsum_b[i] = a2[i] + b2[i]; }
}

// ---------------- split-bf16 tensor-core GEMM (mma.sync, baseline PTX) ----------------
struct GemmP {
    const __nv_bfloat16 *Ah[2], *Al[2], *Bh[2], *Bl[2];
    int K[2], lda[2], ldb[2];
    long sA[2], sB[2];
    int nt;
    float* C; int ldc; long sC;
    const float* bias;
    __nv_bfloat16 *Chi, *Clo; int ldhl; long sHL;
};

#define SROW   40
#define TILEB  (128*SROW*2)
#define STAGEB (4*TILEB)
#define GEMM_SMEM (2*STAGEB)

__device__ __forceinline__ uint32_t smem_u32_of(const void* p) {
    uint32_t a;
    asm("{ .reg .u64 t; cvta.to.shared.u64 t, %1; cvt.u32.u64 %0, t; }" : "=r"(a) : "l"(p));
    return a;
}
__device__ __forceinline__ void cpasync16(uint32_t s, const void* g) {
    asm volatile("cp.async.cg.shared.global [%0], [%1], 16;" :: "r"(s), "l"(g));
}
__device__ __forceinline__ void cpcommit() { asm volatile("cp.async.commit_group;"); }
template<int N> __device__ __forceinline__ void cpwait() {
    asm volatile("cp.async.wait_group %0;" :: "n"(N));
}

#define MMA16816(d, a, b0v, b1v) \
    asm volatile("mma.sync.aligned.m16n8k16.row.col.f32.bf16.bf16.f32 " \
        "{%0,%1,%2,%3}, {%4,%5,%6,%7}, {%8,%9}, {%0,%1,%2,%3};" \
        : "+f"((d)[0]), "+f"((d)[1]), "+f"((d)[2]), "+f"((d)[3]) \
        : "r"((a)[0]), "r"((a)[1]), "r"((a)[2]), "r"((a)[3]), "r"(b0v), "r"(b1v))

__device__ __forceinline__ void issue_stage(
    const GemmP& P, int z, int c, int nc0, int buf,
    int tid, int bm, int bn, uint32_t sbase)
{
    int t  = (c < nc0) ? 0 : 1;
    int ch = (c < nc0) ? c : (c - nc0);
    const __nv_bfloat16* Ah = P.Ah[t] + (long)z * P.sA[t];
    const __nv_bfloat16* Al = P.Al[t] + (long)z * P.sA[t];
    const __nv_bfloat16* Bh = P.Bh[t] + (long)z * P.sB[t];
    const __nv_bfloat16* Bl = P.Bl[t] + (long)z * P.sB[t];
    int lda = P.lda[t], ldb = P.ldb[t];
    int kb0 = ch * 32;
#pragma unroll
    for (int i = 0; i < 8; i++) {
        int idx  = i * 256 + tid;
        int tile = idx >> 9;
        int cc   = idx & 511;
        int row  = cc >> 2;
        int seg  = cc & 3;
        uint32_t sa = sbase + buf * STAGEB + tile * TILEB + (row * SROW + seg * 8) * 2;
        int kb = kb0 + seg * 8;
        const __nv_bfloat16* src;
        if      (tile == 0) src = Ah + (long)(bm + row) * lda + kb;
        else if (tile == 1) src = Al + (long)(bm + row) * lda + kb;
        else if (tile == 2) src = Bh + (long)(bn + row) * ldb + kb;
        else                src = Bl + (long)(bn + row) * ldb + kb;
        cpasync16(sa, src);
    }
    cpcommit();
}

template<bool TANH, bool WF32, bool WBF16>
__global__ void __launch_bounds__(256, 2) mma_gemm_kernel(GemmP P) {
    extern __shared__ __align__(16) char smem[];
    const int tid = threadIdx.x, lane = tid & 31, wid = tid >> 5;
    const int g = lane >> 2, tg = lane & 3;
    const int wm = (wid & 3) * 32, wn = (wid >> 2) * 64;
    const int bn = blockIdx.x * 128, bm = blockIdx.y * 128, z = blockIdx.z;
    const uint32_t sbase = smem_u32_of(smem);

    float acc[2][8][4];
#pragma unroll
    for (int mt = 0; mt < 2; mt++)
#pragma unroll
        for (int nt = 0; nt < 8; nt++)
#pragma unroll
            for (int r = 0; r < 4; r++) acc[mt][nt][r] = 0.f;

    const int nc0 = P.K[0] >> 5;
    const int nct = nc0 + ((P.nt > 1) ? (P.K[1] >> 5) : 0);

    issue_stage(P, z, 0, nc0, 0, tid, bm, bn, sbase);

    for (int c = 0; c < nct; c++) {
        int buf = c & 1;
        if (c + 1 < nct) { issue_stage(P, z, c + 1, nc0, buf ^ 1, tid, bm, bn, sbase); cpwait<1>(); }
        else             { cpwait<0>(); }
        __syncthreads();

        const __nv_bfloat16* Ash = (const __nv_bfloat16*)(smem + buf * STAGEB);
        const __nv_bfloat16* Asl = Ash + 128 * SROW;
        const __nv_bfloat16* Bsh = Asl + 128 * SROW;
        const __nv_bfloat16* Bsl = Bsh + 128 * SROW;

#pragma unroll
        for (int s = 0; s < 2; s++) {
            int k0 = s * 16;
            uint32_t ah[2][4], al[2][4];
#pragma unroll
            for (int mt = 0; mt < 2; mt++) {
                int r = wm + mt * 16 + g;
                ah[mt][0] = *(const uint32_t*)&Ash[(r    ) * SROW + k0     + tg * 2];
                ah[mt][1] = *(const uint32_t*)&Ash[(r + 8) * SROW + k0     + tg * 2];
                ah[mt][2] = *(const uint32_t*)&Ash[(r    ) * SROW + k0 + 8 + tg * 2];
                ah[mt][3] = *(const uint32_t*)&Ash[(r + 8) * SROW + k0 + 8 + tg * 2];
                al[mt][0] = *(const uint32_t*)&Asl[(r    ) * SROW + k0     + tg * 2];
                al[mt][1] = *(const uint32_t*)&Asl[(r + 8) * SROW + k0     + tg * 2];
                al[mt][2] = *(const uint32_t*)&Asl[(r    ) * SROW + k0 + 8 + tg * 2];
                al[mt][3] = *(const uint32_t*)&Asl[(r + 8) * SROW + k0 + 8 + tg * 2];
            }
#pragma unroll
            for (int nt = 0; nt < 8; nt++) {
                int n = wn + nt * 8 + g;
                uint32_t bh0 = *(const uint32_t*)&Bsh[n * SROW + k0     + tg * 2];
                uint32_t bh1 = *(const uint32_t*)&Bsh[n * SROW + k0 + 8 + tg * 2];
                uint32_t bl0 = *(const uint32_t*)&Bsl[n * SROW + k0     + tg * 2];
                uint32_t bl1 = *(const uint32_t*)&Bsl[n * SROW + k0 + 8 + tg * 2];
#pragma unroll
                for (int mt = 0; mt < 2; mt++) {
                    MMA16816(acc[mt][nt], ah[mt], bh0, bh1);
                    MMA16816(acc[mt][nt], ah[mt], bl0, bl1);
                    MMA16816(acc[mt][nt], al[mt], bh0, bh1);
                }
            }
        }
        __syncthreads();
    }

#pragma unroll
    for (int mt = 0; mt < 2; mt++) {
#pragma unroll
        for (int nt = 0; nt < 8; nt++) {
            int col = bn + wn + nt * 8 + tg * 2;
            float bv0 = P.bias ? P.bias[col]     : 0.f;
            float bv1 = P.bias ? P.bias[col + 1] : 0.f;
#pragma unroll
            for (int h = 0; h < 2; h++) {
                int row = bm + wm + mt * 16 + g + h * 8;
                float v0 = acc[mt][nt][h * 2]     + bv0;
                float v1 = acc[mt][nt][h * 2 + 1] + bv1;
                if (TANH) { v0 = tanhf(v0); v1 = tanhf(v1); }
                if (WF32) {
                    float* cp = P.C + (long)z * P.sC + (long)row * P.ldc + col;
                    cp[0] = v0; cp[1] = v1;
                }
                if (WBF16) {
                    long o = (long)z * P.sHL + (long)row * P.ldhl + col;
                    __nv_bfloat16 h0 = __float2bfloat16(v0);
                    __nv_bfloat16 h1 = __float2bfloat16(v1);
                    P.Chi[o] = h0; P.Chi[o + 1] = h1;
                    P.Clo[o]     = __float2bfloat16(v0 - __bfloat162float(h0));
                    P.Clo[o + 1] = __float2bfloat16(v1 - __bfloat162float(h1));
                }
            }
        }
    }
}

// ---------------- persistent bidirectional LSTM (tensor-core, full-K, 1 barrier/step) ----------------
__device__ __forceinline__ void gbar(unsigned bc) {
    __threadfence();
    __syncthreads();
    if (threadIdx.x == 0) {
        atomicAdd(&g_bar, 1u);
        unsigned target = bc * NB_LSTM;
        while (*((volatile unsigned*)&g_bar) < target) { __nanosleep(32); }
        __threadfence();
    }
    __syncthreads();
}
__global__ void reset_kernel() { g_bar = 0u; }

// smem layout (bytes)
#define LS_WS_H 0
#define LS_WS_L 33280
#define LS_HS_H 66560
#define LS_HS_L 133120
#define LS_SG   199680
#define LSTM_SMEM (199680 + 64*33*4)

// 128 blocks = 2 dirs x 64. Block owns 8 hidden units (32 gate-cols) over full K=512.
__global__ void __launch_bounds__(256, 1) lstm_kernel(
    const float* __restrict__ whf, const float* __restrict__ whb)
{
    extern __shared__ __align__(16) char smem[];
    __nv_bfloat16* WS_h = (__nv_bfloat16*)(smem + LS_WS_H);
    __nv_bfloat16* WS_l = (__nv_bfloat16*)(smem + LS_WS_L);
    __nv_bfloat16* HS_h = (__nv_bfloat16*)(smem + LS_HS_H);
    __nv_bfloat16* HS_l = (__nv_bfloat16*)(smem + LS_HS_L);
    float* SG = (float*)(smem + LS_SG);          // [64][33] gate sums
    const uint32_t sbase = smem_u32_of(smem);

    const int tid = threadIdx.x, lane = tid & 31, wid = tid >> 5;
    const int g = lane >> 2, tg = lane & 3;
    const int bid = blockIdx.x;
    const int dir = bid >> 6, b64 = bid & 63;
    const float* W    = dir ? whb : whf;           // [2048][512]
    const float* xpre = dir ? g_xpre_b : g_xpre_f;

    // preload W slice: rows r = gate*8 + j  (gate-col = gate*512 + b64*8 + j), split bf16
    for (int idx = tid; idx < 32 * 512; idx += 256) {
        int r = idx >> 9, k = idx & 511;
        int gg = r >> 3, j = r & 7;
        float v = W[(long)(gg * H_ + b64 * 8 + j) * H_ + k];
        __nv_bfloat16 h = __float2bfloat16(v);
        WS_h[r * 520 + k] = h;
        WS_l[r * 520 + k] = __float2bfloat16(v - __bfloat162float(h));
    }
    __syncthreads();

    const int m0 = (wid & 3) * 16, n0 = (wid >> 2) * 16;   // 8 warps: 4m x 2n, warp tile 16x16
    // cell mapping: 2 values per thread, consecutive uj
    const int v0 = tid * 2;
    const int ub0 = v0 >> 3, uj0 = v0 & 7;
    const int col0 = b64 * 8 + uj0;
    float creg0 = 0.f, creg1 = 0.f;
    unsigned bc = 0;

    for (int s = 0; s < T_; s++) {
        int t = dir ? (T_ - 1 - s) : s;
        int wbuf = s & 1, rbuf = wbuf ^ 1;

        // prefetch xpre gates for this thread's 2 cells (independent of h)
        float xg0[4], xg1[4];
        {
            const float* xp = xpre + ((long)ub0 * T_ + t) * G_ + b64 * 8 + uj0;
#pragma unroll
            for (int q = 0; q < 4; q++) { xg0[q] = __ldcg(&xp[q * H_]); xg1[q] = __ldcg(&xp[q * H_ + 1]); }
        }

        if (s > 0) {
            // stage h (prev step) from global split-bf16 into smem
            const __nv_bfloat16* Hh = g_hhi[dir][rbuf];
            const __nv_bfloat16* Hl = g_hlo[dir][rbuf];
            for (int c = tid; c < 8192; c += 256) {
                int arr = c >> 12;
                int cc  = c & 4095;
                int row = cc >> 6, seg = cc & 63;
                uint32_t sa = sbase + (arr ? LS_HS_L : LS_HS_H) + row * 1040 + seg * 16;
                const __nv_bfloat16* src = (arr ? Hl : Hh) + row * H_ + seg * 8;
                cpasync16(sa, src);
            }
            cpcommit(); cpwait<0>();
            __syncthreads();

            float acc[2][4];
#pragma unroll
            for (int nt = 0; nt < 2; nt++)
#pragma unroll
                for (int r = 0; r < 4; r++) acc[nt][r] = 0.f;

#pragma unroll 4
            for (int ks = 0; ks < 32; ks++) {
                int kw = ks * 16;
                uint32_t ah[4], al[4];
                ah[0] = *(const uint32_t*)&HS_h[(m0 + g    ) * 520 + kw     + tg * 2];
                ah[1] = *(const uint32_t*)&HS_h[(m0 + g + 8) * 520 + kw     + tg * 2];
                ah[2] = *(const uint32_t*)&HS_h[(m0 + g    ) * 520 + kw + 8 + tg * 2];
                ah[3] = *(const uint32_t*)&HS_h[(m0 + g + 8) * 520 + kw + 8 + tg * 2];
                al[0] = *(const uint32_t*)&HS_l[(m0 + g    ) * 520 + kw     + tg * 2];
                al[1] = *(const uint32_t*)&HS_l[(m0 + g + 8) * 520 + kw     + tg * 2];
                al[2] = *(const uint32_t*)&HS_l[(m0 + g    ) * 520 + kw + 8 + tg * 2];
                al[3] = *(const uint32_t*)&HS_l[(m0 + g + 8) * 520 + kw + 8 + tg * 2];
#pragma unroll
                for (int nt = 0; nt < 2; nt++) {
                    int n = n0 + nt * 8 + g;
                    uint32_t bh0 = *(const uint32_t*)&WS_h[n * 520 + kw     + tg * 2];
                    uint32_t bh1 = *(const uint32_t*)&WS_h[n * 520 + kw + 8 + tg * 2];
                    uint32_t bl0 = *(const uint32_t*)&WS_l[n * 520 + kw     + tg * 2];
                    uint32_t bl1 = *(const uint32_t*)&WS_l[n * 520 + kw + 8 + tg * 2];
                    MMA16816(acc[nt], ah, bh0, bh1);
                    MMA16816(acc[nt], ah, bl0, bl1);
                    MMA16816(acc[nt], al, bh0, bh1);
                }
            }
            // route accumulators to SG[batch][gatecol 0..31]
#pragma unroll
            for (int nt = 0; nt < 2; nt++) {
                int col = n0 + nt * 8 + tg * 2;
                SG[(m0 + g    ) * 33 + col    ] = acc[nt][0];
                SG[(m0 + g    ) * 33 + col + 1] = acc[nt][1];
                SG[(m0 + g + 8) * 33 + col    ] = acc[nt][2];
                SG[(m0 + g + 8) * 33 + col + 1] = acc[nt][3];
            }
            __syncthreads();
        }

        // cell update (2 values per thread)
        {
            float gv0[4], gv1[4];
#pragma unroll
            for (int q = 0; q < 4; q++) {
                float a0 = xg0[q], a1 = xg1[q];
                if (s > 0) {
                    a0 += SG[ub0 * 33 + q * 8 + uj0];
                    a1 += SG[ub0 * 33 + q * 8 + uj0 + 1];
                }
                gv0[q] = a0; gv1[q] = a1;
            }
            float i0 = 1.f / (1.f + expf(-gv0[0]));
            float f0 = 1.f / (1.f + expf(-gv0[1]));
            float c0 = tanhf(gv0[2]);
            float o0 = 1.f / (1.f + expf(-gv0[3]));
            creg0 = f0 * creg0 + i0 * c0;
            float h0 = o0 * tanhf(creg0);

            float i1 = 1.f / (1.f + expf(-gv1[0]));
            float f1 = 1.f / (1.f + expf(-gv1[1]));
            float c1 = tanhf(gv1[2]);
            float o1 = 1.f / (1.f + expf(-gv1[3]));
            creg1 = f1 * creg1 + i1 * c1;
            float h1 = o1 * tanhf(creg1);

            long co = ((long)ub0 * T_ + t) * D_ + dir * H_ + col0;
            g_ctx[co]     = h0;
            g_ctx[co + 1] = h1;
            __nv_bfloat16* Hh = g_hhi[dir][wbuf];
            __nv_bfloat16* Hl = g_hlo[dir][wbuf];
            __nv_bfloat16 hh0 = __float2bfloat16(h0);
            __nv_bfloat16 hh1 = __float2bfloat16(h1);
            Hh[ub0 * H_ + col0]     = hh0;
            Hh[ub0 * H_ + col0 + 1] = hh1;
            Hl[ub0 * H_ + col0]     = __float2bfloat16(h0 - __bfloat162float(hh0));
            Hl[ub0 * H_ + col0 + 1] = __float2bfloat16(h1 - __bfloat162float(hh1));
        }
        gbar(++bc);
    }
}

// ---------------- softmax / mean / head / bn ----------------
__global__ void softmax_kernel(const unsigned char* __restrict__ mask) {
    int row = blockIdx.x;
    int tid = threadIdx.x;
    int b = row >> 8;
    float v = g_scores[(long)row * T_ + tid];
    if (mask[b * T_ + tid]) v = -INFINITY;
    __shared__ float red[256];
    red[tid] = v; __syncthreads();
    for (int s = 128; s > 0; s >>= 1) {
        if (tid < s) red[tid] = fmaxf(red[tid], red[tid + s]);
        __syncthreads();
    }
    float m = red[0]; __syncthreads();
    float e = __expf(v - m);
    red[tid] = e; __syncthreads();
    for (int s = 128; s > 0; s >>= 1) {
        if (tid < s) red[tid] += red[tid + s];
        __syncthreads();
    }
    g_scores[(long)row * T_ + tid] = e / red[0];
}

__global__ void mean_kernel() {
    int idx = blockIdx.x * 256 + threadIdx.x;
    int b = idx >> 10, d = idx & 1023;
    const float* p = &g_htilde[(long)b * T_ * D_ + d];
    float s = 0.f;
    for (int t = 0; t < T_; t++) s += p[(long)t * D_];
    g_ctxout[idx] = s * (1.0f / T_);
}

__global__ void yhead_kernel(const float* __restrict__ w_out, const float* __restrict__ b_out) {
    int m = blockIdx.x, tid = threadIdx.x;
    int wid = tid >> 5, lid = tid & 31;
    const float* x = &g_ctxout[m * D_];
    for (int n = wid; n < OUT_; n += 8) {
        const float* w = &w_out[(long)n * D_];
        float s = 0.f;
        for (int k = lid; k < D_; k += 32) s += x[k] * w[k];
#pragma unroll
        for (int o = 16; o > 0; o >>= 1) s += __shfl_down_sync(0xffffffffu, s, o);
        if (lid == 0) g_y[m * OUT_ + n] = tanhf(s + b_out[n]);
    }
}

__global__ void bn_kernel(const float* __restrict__ gamma, const float* __restrict__ beta,
                          float* __restrict__ out) {
    int n = threadIdx.x;
    float mu = 0.f;
    for (int b = 0; b < B_; b++) mu += g_y[b * OUT_ + n];
    mu *= (1.0f / B_);
    float var = 0.f;
    for (int b = 0; b < B_; b++) { float d = g_y[b * OUT_ + n] - mu; var += d * d; }
    var *= (1.0f / B_);
    float inv = rsqrtf(var + 1e-5f);
    float ga = gamma[n], be = beta[n];
    for (int b = 0; b < B_; b++)
        out[b * OUT_ + n] = ga * (g_y[b * OUT_ + n] - mu) * inv + be;
}

// ---------------- host launcher ----------------
static inline void conv(const float* s, __nv_bfloat16* h, __nv_bfloat16* l,
                        int rows, int scols, int sld, int dld) {
    long tot = (long)rows * dld;
    conv_kernel<<<(unsigned)((tot + 255) / 256), 256>>>(s, h, l, rows, scols, sld, dld);
}

extern "C" void kernel_launch(void* const* d_in, const int* in_sizes, int n_in,
                              void* d_out, int out_size) {
    const int*   inputs = (const int*)d_in[0];
    const unsigned char* mask = (const unsigned char*)d_in[1];
    const float* table  = (const float*)d_in[2];
    const float* w_ih_f = (const float*)d_in[3];
    const float* w_hh_f = (const float*)d_in[4];
    const float* b_ih_f = (const float*)d_in[5];
    const float* b_hh_f = (const float*)d_in[6];
    const float* w_ih_b = (const float*)d_in[7];
    const float* w_hh_b = (const float*)d_in[8];
    const float* b_ih_b = (const float*)d_in[9];
    const float* b_hh_b = (const float*)d_in[10];
    const float* w_in   = (const float*)d_in[11];
    const float* w_attn = (const float*)d_in[12];
    const float* w_out  = (const float*)d_in[13];
    const float* b_out  = (const float*)d_in[14];
    const float* gamma  = (const float*)d_in[15];
    const float* beta   = (const float*)d_in[16];
    float* out = (float*)d_out;

    float *embeds, *xf, *xb, *ctx, *scores, *htilde, *bsf, *bsb;
    cudaGetSymbolAddress((void**)&embeds, g_embeds);
    cudaGetSymbolAddress((void**)&xf,     g_xpre_f);
    cudaGetSymbolAddress((void**)&xb,     g_xpre_b);
    cudaGetSymbolAddress((void**)&ctx,    g_ctx);
    cudaGetSymbolAddress((void**)&scores, g_scores);
    cudaGetSymbolAddress((void**)&htilde, g_htilde);
    cudaGetSymbolAddress((void**)&bsf,    g_bsum_f);
    cudaGetSymbolAddress((void**)&bsb,    g_bsum_b);
    __nv_bfloat16 *eh,*el,*wfh,*wfl,*wbh,*wbl,*ch,*cl,*cth,*ctl,*winh,*winl,
                  *th,*tl,*ah,*al,*w1h,*w1l,*w2h,*w2l,*wh,*wl;
    cudaGetSymbolAddress((void**)&eh, g_eh);   cudaGetSymbolAddress((void**)&el, g_el);
    cudaGetSymbolAddress((void**)&wfh, g_wfh); cudaGetSymbolAddress((void**)&wfl, g_wfl);
    cudaGetSymbolAddress((void**)&wbh, g_wbh); cudaGetSymbolAddress((void**)&wbl, g_wbl);
    cudaGetSymbolAddress((void**)&ch, g_ch);   cudaGetSymbolAddress((void**)&cl, g_cl);
    cudaGetSymbolAddress((void**)&cth, g_cth); cudaGetSymbolAddress((void**)&ctl, g_ctl);
    cudaGetSymbolAddress((void**)&winh, g_winh); cudaGetSymbolAddress((void**)&winl, g_winl);
    cudaGetSymbolAddress((void**)&th, g_th);   cudaGetSymbolAddress((void**)&tl, g_tl);
    cudaGetSymbolAddress((void**)&ah, g_ah);   cudaGetSymbolAddress((void**)&al, g_al);
    cudaGetSymbolAddress((void**)&w1h, g_w1h); cudaGetSymbolAddress((void**)&w1l, g_w1l);
    cudaGetSymbolAddress((void**)&w2h, g_w2h); cudaGetSymbolAddress((void**)&w2l, g_w2l);
    cudaGetSymbolAddress((void**)&wh, g_wh);   cudaGetSymbolAddress((void**)&wl, g_wl);

    cudaFuncSetAttribute(mma_gemm_kernel<false,true,false>,
                         cudaFuncAttributeMaxDynamicSharedMemorySize, GEMM_SMEM);
    cudaFuncSetAttribute(mma_gemm_kernel<false,false,true>,
                         cudaFuncAttributeMaxDynamicSharedMemorySize, GEMM_SMEM);
    cudaFuncSetAttribute(mma_gemm_kernel<true,true,false>,
                         cudaFuncAttributeMaxDynamicSharedMemorySize, GEMM_SMEM);

    // 1. embed + operand conversions
    embed_kernel<<<(BT_*E_ + 255) / 256, 256>>>(inputs, table);
    conv(embeds, eh, el, BT_, E_, E_, EP_);
    conv(w_ih_f, wfh, wfl, G_, E_, E_, EP_);
    conv(w_ih_b, wbh, wbl, G_, E_, E_, EP_);
    conv(w_in,   winh, winl, D_, D_, D_, D_);
    conv(w_attn,        w1h, w1l, D_, D_, 2*D_, D_);
    conv(w_attn + D_,   w2h, w2l, D_, D_, 2*D_, D_);
    bsum_kernel<<<(G_ + 255) / 256, 256>>>(b_ih_f, b_hh_f, b_ih_b, b_hh_b);

    // 2. xpre = embeds @ w_ih^T + (b_ih + b_hh)
    {
        GemmP P{};
        P.nt = 1; P.K[0] = EP_; P.lda[0] = EP_; P.ldb[0] = EP_;
        P.Ah[0] = eh; P.Al[0] = el; P.ldc = G_;
        P.Bh[0] = wfh; P.Bl[0] = wfl; P.C = xf; P.bias = bsf;
        dim3 g(G_/128, BT_/128, 1);
        mma_gemm_kernel<false,true,false><<<g, 256, GEMM_SMEM>>>(P);
        P.Bh[0] = wbh; P.Bl[0] = wbl; P.C = xb; P.bias = bsb;
        mma_gemm_kernel<false,true,false><<<g, 256, GEMM_SMEM>>>(P);
    }

    // 3. persistent bidirectional LSTM (tensor-core, 1 barrier/step)
    reset_kernel<<<1, 1>>>();
    cudaFuncSetAttribute(lstm_kernel, cudaFuncAttributeMaxDynamicSharedMemorySize, LSTM_SMEM);
    lstm_kernel<<<NB_LSTM, 256, LSTM_SMEM>>>(w_hh_f, w_hh_b);

    // 4. ctx conversions
    conv(ctx, ch, cl, BT_, D_, D_, D_);
    tconv_kernel<<<dim3(T_/32, D_/32, B_), dim3(32, 8)>>>(ctx, cth, ctl);

    // 5. target = ctx @ w_in^T  (bf16 hi/lo out)
    {
        GemmP P{};
        P.nt = 1; P.K[0] = D_; P.lda[0] = D_; P.ldb[0] = D_;
        P.Ah[0] = ch; P.Al[0] = cl; P.Bh[0] = winh; P.Bl[0] = winl;
        P.Chi = th; P.Clo = tl; P.ldhl = D_;
        dim3 g(D_/128, BT_/128, 1);
        mma_gemm_kernel<false,false,true><<<g, 256, GEMM_SMEM>>>(P);
    }

    // 6. scores[z] = target[z] @ ctx[z]^T  (fp32 out)
    {
        GemmP P{};
        P.nt = 1; P.K[0] = D_; P.lda[0] = D_; P.ldb[0] = D_;
        P.Ah[0] = th; P.Al[0] = tl; P.sA[0] = (long)T_*D_;
        P.Bh[0] = ch; P.Bl[0] = cl; P.sB[0] = (long)T_*D_;
        P.C = scores; P.ldc = T_; P.sC = (long)T_*T_;
        dim3 g(T_/128, T_/128, B_);
        mma_gemm_kernel<false,true,false><<<g, 256, GEMM_SMEM>>>(P);
    }

    // 7. softmax + attn split
    softmax_kernel<<<BT_, 256>>>(mask);
    conv(scores, ah, al, BT_, T_, T_, T_);

    // 8. weighted[z] = attn[z] @ ctxT[z]^T  (bf16 hi/lo out)
    {
        GemmP P{};
        P.nt = 1; P.K[0] = T_; P.lda[0] = T_; P.ldb[0] = T_;
        P.Ah[0] = ah; P.Al[0] = al; P.sA[0] = (long)T_*T_;
        P.Bh[0] = cth; P.Bl[0] = ctl; P.sB[0] = (long)D_*T_;
        P.Chi = wh; P.Clo = wl; P.ldhl = D_; P.sHL = (long)T_*D_;
        dim3 g(D_/128, T_/128, B_);
        mma_gemm_kernel<false,false,true><<<g, 256, GEMM_SMEM>>>(P);
    }

    // 9. htilde = tanh(weighted @ W1^T + ctx @ W2^T)
    {
        GemmP P{};
        P.nt = 2;
        P.K[0] = D_; P.lda[0] = D_; P.ldb[0] = D_;
        P.Ah[0] = wh; P.Al[0] = wl; P.Bh[0] = w1h; P.Bl[0] = w1l;
        P.K[1] = D_; P.lda[1] = D_; P.ldb[1] = D_;
        P.Ah[1] = ch; P.Al[1] = cl; P.Bh[1] = w2h; P.Bl[1] = w2l;
        P.C = htilde; P.ldc = D_;
        dim3 g(D_/128, BT_/128, 1);
        mma_gemm_kernel<true,true,false><<<g, 256, GEMM_SMEM>>>(P);
    }

    // 10-12. mean, head, batchnorm
    mean_kernel<<<(B_*D_)/256, 256>>>();
    yhead_kernel<<<B_, 256>>>(w_out, b_out);
    bn_kernel<<<1, OUT_>>>(gamma, beta, out);
}